// round 5
// baseline (speedup 1.0000x reference)
#include <cuda_runtime.h>
#include <cstdint>

// ChebConv, commuted form:
//   Agg[row, f] = sum_{e: rows[e]=row} vals[e] * x_flat[512*cols[e] + f],  f in [0,512)
//   out[row*1536 + j*192 + q] = sum_k Agg[row, j*64+k] * W2[k,q] + bias[q&63]
#define N_VERTEX 2048
#define NNZ_MAX  98304
#define ROW_LEN  1536
#define KCOLS    192
#define NSUB     4
#define SUB_CAP  48
#define SLOTS    (NSUB * SUB_CAP)
#define TP       12            // transposed-Agg stride: 48B rows -> 16B-aligned LDS.128

__device__ int    g_cnt[N_VERTEX * NSUB];
__device__ float2 g_edge[N_VERTEX * NSUB * SUB_CAP];   // (val, byte-offset bits)
__device__ float2 g_wT2[KCOLS * 64];                   // wT2[q*64+k] = (w[k][q], w[k][q])

typedef unsigned long long u64;

__device__ __forceinline__ u64 pk2(float a, float b) {
    u64 r; asm("mov.b64 %0, {%1, %2};" : "=l"(r) : "f"(a), "f"(b)); return r;
}
__device__ __forceinline__ u64 fma2(u64 a, u64 b, u64 c) {
    u64 d; asm("fma.rn.f32x2 %0, %1, %2, %3;" : "=l"(d) : "l"(a), "l"(b), "l"(c)); return d;
}

// Prepass: transpose + duplicate weights (12288 threads, trivial).
__global__ void k_wprep(const float* __restrict__ w) {
    int i = blockIdx.x * blockDim.x + threadIdx.x;   // i = q*64 + k
    if (i < KCOLS * 64) {
        int q = i >> 6, k = i & 63;
        float v = w[k * KCOLS + q];
        g_wT2[i] = make_float2(v, v);
    }
}

// Bucket scatter, 4-way split counters.
__global__ void k_scatter(const float* __restrict__ vals,
                          const int*   __restrict__ rows,
                          const int*   __restrict__ cols, int nnz) {
    int i = blockIdx.x * blockDim.x + threadIdx.x;
    if (i < nnz) {
        int r   = rows[i];
        int sub = i & (NSUB - 1);
        int p   = atomicAdd(&g_cnt[r * NSUB + sub], 1);
        if (p < SUB_CAP)
            g_edge[(r * NSUB + sub) * SUB_CAP + p] =
                make_float2(vals[i], __int_as_float(cols[i] * 2048));
    }
}

// One block (256 threads) per row.
__global__ __launch_bounds__(256) void k_main(
    const float* __restrict__ x,
    const float* __restrict__ bias,
    float* __restrict__ out)
{
    __shared__ alignas(16) float sT[2][64 * TP];   // transposed partials (addr = TP*k + j)
    __shared__ float2 sE[SLOTS];
    __shared__ int    sCnt[NSUB];

    const int row = blockIdx.x;
    const int tid = threadIdx.x;

    if (tid < NSUB) {
        int c = g_cnt[row * NSUB + tid];
        sCnt[tid] = (c > SUB_CAP) ? SUB_CAP : c;
        g_cnt[row * NSUB + tid] = 0;               // restore invariant for replay
    }
    __syncthreads();

    const int c0 = sCnt[0], c1 = sCnt[1], c2 = sCnt[2], c3 = sCnt[3];
    const int deg = c0 + c1 + c2 + c3;             // <= 192

    if (tid < deg) {
        int b, pos;
        if      (tid < c0)           { b = 0; pos = tid; }
        else if (tid < c0 + c1)      { b = 1; pos = tid - c0; }
        else if (tid < c0 + c1 + c2) { b = 2; pos = tid - c0 - c1; }
        else                         { b = 3; pos = tid - c0 - c1 - c2; }
        sE[tid] = g_edge[(row * NSUB + b) * SUB_CAP + pos];
    }
    __syncthreads();

    // ---- Phase 1: gather-aggregate (f32x2 FMAs, 8 LDG.128 in flight) ----
    const int lane = tid & 127;                    // owns floats 4*lane .. 4*lane+3
    const int grp  = tid >> 7;
    u64 a01 = 0ull, a23 = 0ull;
    const char* xb = (const char*)x + lane * 16;
    #pragma unroll 8
    for (int i = grp; i < deg; i += 2) {
        float2 ed = sE[i];                                       // LDS.64 broadcast
        const ulonglong2 d = *(const ulonglong2*)(xb + __float_as_int(ed.y)); // LDG.128
        u64 vd = pk2(ed.x, ed.x);
        a01 = fma2(d.x, vd, a01);
        a23 = fma2(d.y, vd, a23);
    }
    {
        const int j  = (4 * lane) >> 6;
        const int k0 = (4 * lane) & 63;
        float* dst = sT[grp];
        float f0, f1, f2, f3;
        asm("mov.b64 {%0, %1}, %2;" : "=f"(f0), "=f"(f1) : "l"(a01));
        asm("mov.b64 {%0, %1}, %2;" : "=f"(f2), "=f"(f3) : "l"(a23));
        dst[TP * k0 + j]       = f0;
        dst[TP * (k0 + 1) + j] = f1;
        dst[TP * (k0 + 2) + j] = f2;
        dst[TP * (k0 + 3) + j] = f3;
    }
    __syncthreads();
    {   // merge the two partials (768 floats)
        float* a = sT[0]; const float* b = sT[1];
        #pragma unroll
        for (int i = tid; i < 64 * TP; i += 256) a[i] += b[i];
    }
    __syncthreads();

    // ---- Phase 2: [8,64]@[64,192]; j-paired f32x2, zero packing movs ----
    if (tid < KCOLS) {
        const int q = tid;
        u64 acc0 = 0ull, acc1 = 0ull, acc2 = 0ull, acc3 = 0ull;
        const float2* wq = &g_wT2[q * 64];         // contiguous 512B, L1/L2-resident
        const float*  ag = sT[0];
        #pragma unroll 4
        for (int k = 0; k < 64; k += 2) {
            ulonglong2 wd = *(const ulonglong2*)(wq + k);        // (wk,wk),(wk1,wk1)
            ulonglong2 b0 = *(const ulonglong2*)(ag + TP * k);       // (j0,j1),(j2,j3)
            ulonglong2 b1 = *(const ulonglong2*)(ag + TP * k + 4);   // (j4,j5),(j6,j7)
            ulonglong2 b2 = *(const ulonglong2*)(ag + TP * (k + 1));
            ulonglong2 b3 = *(const ulonglong2*)(ag + TP * (k + 1) + 4);
            acc0 = fma2(b0.x, wd.x, acc0);
            acc1 = fma2(b0.y, wd.x, acc1);
            acc2 = fma2(b1.x, wd.x, acc2);
            acc3 = fma2(b1.y, wd.x, acc3);
            acc0 = fma2(b2.x, wd.y, acc0);
            acc1 = fma2(b2.y, wd.y, acc1);
            acc2 = fma2(b3.x, wd.y, acc2);
            acc3 = fma2(b3.y, wd.y, acc3);
        }
        const float bv = __ldg(&bias[q & 63]);
        float* op = out + (size_t)row * ROW_LEN + q;
        u64 accs[4] = {acc0, acc1, acc2, acc3};
        #pragma unroll
        for (int p = 0; p < 4; ++p) {
            float lo, hi;
            asm("mov.b64 {%0, %1}, %2;" : "=f"(lo), "=f"(hi) : "l"(accs[p]));
            op[(2 * p)     * KCOLS] = lo + bv;
            op[(2 * p + 1) * KCOLS] = hi + bv;
        }
    }
}

extern "C" void kernel_launch(void* const* d_in, const int* in_sizes, int n_in,
                              void* d_out, int out_size) {
    const float* x    = (const float*)d_in[0];
    const float* w    = (const float*)d_in[1];
    const float* bias = (const float*)d_in[2];
    const float* fv   = (const float*)d_in[3];
    const int*   fr   = (const int*)d_in[4];
    const int*   fc   = (const int*)d_in[5];
    int nnz = in_sizes[3];
    if (nnz > NNZ_MAX) nnz = NNZ_MAX;
    float* out = (float*)d_out;

    k_wprep  <<<(KCOLS * 64 + 255) / 256, 256>>>(w);
    k_scatter<<<(nnz + 255) / 256, 256>>>(fv, fr, fc, nnz);
    k_main   <<<N_VERTEX, 256>>>(x, bias, out);
}

// round 6
// speedup vs baseline: 1.8642x; 1.8642x over previous
#include <cuda_runtime.h>
#include <cuda_fp16.h>
#include <cstdint>

// ChebConv, commuted:
//   Agg[row, f] = sum_{e: rows[e]=row} vals[e] * x_flat[512*cols[e] + f]   (f in [0,512))
//   out[row*1536 + j*192 + q] = sum_k Agg[row, j*64+k] * w[k*192+q] + bias[q&63]
// Gather done on fp16 copy of x (halves L1/L2 traffic); all accumulation fp32.
#define N_VERTEX 2048
#define NNZ_MAX  98304
#define ROW_LEN  1536
#define KCOLS    192
#define NSUB     4
#define SUB_CAP  48
#define SLOTS    (NSUB * SUB_CAP)
#define TP       12
#define X_ELEMS  3145728

__device__ int    g_cnt[N_VERTEX * NSUB];
__device__ float2 g_edge[N_VERTEX * NSUB * SUB_CAP];      // (val, byte-offset bits)
__device__ __align__(16) __half g_xh[X_ELEMS];            // 6MB fp16 copy of x
__device__ __align__(16) float  g_agg[N_VERTEX * 512];    // 4MB aggregate scratch

typedef unsigned long long u64;
__device__ __forceinline__ u64 pk2(float a, float b) {
    u64 r; asm("mov.b64 %0, {%1, %2};" : "=l"(r) : "f"(a), "f"(b)); return r;
}
__device__ __forceinline__ u64 fma2(u64 a, u64 b, u64 c) {
    u64 d; asm("fma.rn.f32x2 %0, %1, %2, %3;" : "=l"(d) : "l"(a), "l"(b), "l"(c)); return d;
}

// x -> fp16 (vectorized: 4 floats -> 4 halfs per thread)
__global__ void k_xhalf(const float* __restrict__ x) {
    int i = blockIdx.x * blockDim.x + threadIdx.x;
    if (i < X_ELEMS / 4) {
        float4 v = reinterpret_cast<const float4*>(x)[i];
        __half2 h0 = __floats2half2_rn(v.x, v.y);
        __half2 h1 = __floats2half2_rn(v.z, v.w);
        uint2 p;
        p.x = *reinterpret_cast<unsigned*>(&h0);
        p.y = *reinterpret_cast<unsigned*>(&h1);
        reinterpret_cast<uint2*>(g_xh)[i] = p;
    }
}

// Bucket scatter, 4-way split counters. Stores BYTE offset into g_xh (col*512*2).
__global__ void k_scatter(const float* __restrict__ vals,
                          const int*   __restrict__ rows,
                          const int*   __restrict__ cols, int nnz) {
    int i = blockIdx.x * blockDim.x + threadIdx.x;
    if (i < nnz) {
        int r   = rows[i];
        int sub = i & (NSUB - 1);
        int p   = atomicAdd(&g_cnt[r * NSUB + sub], 1);
        if (p < SUB_CAP)
            g_edge[(r * NSUB + sub) * SUB_CAP + p] =
                make_float2(vals[i], __int_as_float(cols[i] * 1024));
    }
}

// Gather-aggregate: one block per row; 64 lanes (16B = 8 halfs each) x 4 edge-groups.
__global__ __launch_bounds__(256) void k_gather() {
    __shared__ float2 sE[SLOTS];
    __shared__ int    sCnt[NSUB];
    __shared__ alignas(16) float sP[4][512];

    const int row = blockIdx.x;
    const int tid = threadIdx.x;

    if (tid < NSUB) {
        int c = g_cnt[row * NSUB + tid];
        sCnt[tid] = (c > SUB_CAP) ? SUB_CAP : c;
        g_cnt[row * NSUB + tid] = 0;             // restore invariant for graph replay
    }
    __syncthreads();
    const int c0 = sCnt[0], c1 = sCnt[1], c2 = sCnt[2], c3 = sCnt[3];
    const int deg = c0 + c1 + c2 + c3;           // <= 192

    if (tid < deg) {
        int b, pos;
        if      (tid < c0)           { b = 0; pos = tid; }
        else if (tid < c0 + c1)      { b = 1; pos = tid - c0; }
        else if (tid < c0 + c1 + c2) { b = 2; pos = tid - c0 - c1; }
        else                         { b = 3; pos = tid - c0 - c1 - c2; }
        sE[tid] = g_edge[(row * NSUB + b) * SUB_CAP + pos];
    }
    __syncthreads();

    const int lane = tid & 63;                   // owns halfs 8*lane .. 8*lane+7
    const int grp  = tid >> 6;                   // 4 edge-groups
    float a0=0.f,a1=0.f,a2=0.f,a3=0.f,a4=0.f,a5=0.f,a6=0.f,a7=0.f;
    const char* xb = (const char*)g_xh + lane * 16;
    #pragma unroll 6
    for (int i = grp; i < deg; i += 4) {
        float2 ed = sE[i];                                       // LDS.64 broadcast
        uint4 d = *(const uint4*)(xb + __float_as_int(ed.y));    // LDG.128 (8 halfs)
        float v = ed.x;
        float2 f0 = __half22float2(*reinterpret_cast<__half2*>(&d.x));
        float2 f1 = __half22float2(*reinterpret_cast<__half2*>(&d.y));
        float2 f2 = __half22float2(*reinterpret_cast<__half2*>(&d.z));
        float2 f3 = __half22float2(*reinterpret_cast<__half2*>(&d.w));
        a0 = fmaf(v, f0.x, a0); a1 = fmaf(v, f0.y, a1);
        a2 = fmaf(v, f1.x, a2); a3 = fmaf(v, f1.y, a3);
        a4 = fmaf(v, f2.x, a4); a5 = fmaf(v, f2.y, a5);
        a6 = fmaf(v, f3.x, a6); a7 = fmaf(v, f3.y, a7);
    }
    float* sp = &sP[grp][8 * lane];
    *(float4*)(sp)     = make_float4(a0, a1, a2, a3);
    *(float4*)(sp + 4) = make_float4(a4, a5, a6, a7);
    __syncthreads();

    if (tid < 128) {                             // merge 4 partials, store float4
        const int f = 4 * tid;
        float4 p0 = *(const float4*)&sP[0][f];
        float4 p1 = *(const float4*)&sP[1][f];
        float4 p2 = *(const float4*)&sP[2][f];
        float4 p3 = *(const float4*)&sP[3][f];
        float4 s = make_float4((p0.x+p1.x)+(p2.x+p3.x), (p0.y+p1.y)+(p2.y+p3.y),
                               (p0.z+p1.z)+(p2.z+p3.z), (p0.w+p1.w)+(p2.w+p3.w));
        *(float4*)&g_agg[row * 512 + f] = s;
    }
}

// Mini-GEMM per row: [8,64]@[64,192] + bias; j-paired f32x2, coalesced scalar w.
__global__ __launch_bounds__(192) void k_gemm(
    const float* __restrict__ w,
    const float* __restrict__ bias,
    float* __restrict__ out)
{
    __shared__ alignas(16) float sT[64 * TP];    // transposed Agg: addr = TP*k + j
    const int row = blockIdx.x;
    const int tid = threadIdx.x;

    for (int i = tid; i < 512; i += 192)
        sT[TP * (i & 63) + (i >> 6)] = g_agg[row * 512 + i];   // coalesced LDG
    __syncthreads();

    const int q = tid;
    u64 acc0 = 0ull, acc1 = 0ull, acc2 = 0ull, acc3 = 0ull;
    const float* wq = w + q;
    #pragma unroll 4
    for (int k = 0; k < 64; ++k) {
        float wv = __ldg(wq + k * KCOLS);        // one 128B line per warp, L1-resident
        u64 wd = pk2(wv, wv);
        ulonglong2 b0 = *(const ulonglong2*)(sT + TP * k);      // (j0,j1),(j2,j3)
        ulonglong2 b1 = *(const ulonglong2*)(sT + TP * k + 4);  // (j4,j5),(j6,j7)
        acc0 = fma2(b0.x, wd, acc0);
        acc1 = fma2(b0.y, wd, acc1);
        acc2 = fma2(b1.x, wd, acc2);
        acc3 = fma2(b1.y, wd, acc3);
    }
    const float bv = __ldg(&bias[q & 63]);
    float* op = out + (size_t)row * ROW_LEN + q;
    u64 accs[4] = {acc0, acc1, acc2, acc3};
    #pragma unroll
    for (int p = 0; p < 4; ++p) {
        float lo, hi;
        asm("mov.b64 {%0, %1}, %2;" : "=f"(lo), "=f"(hi) : "l"(accs[p]));
        op[(2 * p)     * KCOLS] = lo + bv;
        op[(2 * p + 1) * KCOLS] = hi + bv;
    }
}

extern "C" void kernel_launch(void* const* d_in, const int* in_sizes, int n_in,
                              void* d_out, int out_size) {
    const float* x    = (const float*)d_in[0];
    const float* w    = (const float*)d_in[1];
    const float* bias = (const float*)d_in[2];
    const float* fv   = (const float*)d_in[3];
    const int*   fr   = (const int*)d_in[4];
    const int*   fc   = (const int*)d_in[5];
    int nnz = in_sizes[3];
    if (nnz > NNZ_MAX) nnz = NNZ_MAX;
    float* out = (float*)d_out;

    k_xhalf  <<<(X_ELEMS / 4 + 255) / 256, 256>>>(x);
    k_scatter<<<(nnz + 255) / 256, 256>>>(fv, fr, fc, nnz);
    k_gather <<<N_VERTEX, 256>>>();
    k_gemm   <<<N_VERTEX, 192>>>(w, bias, out);
}

// round 7
// speedup vs baseline: 2.0509x; 1.1002x over previous
#include <cuda_runtime.h>
#include <cuda_fp16.h>
#include <cstdint>

// ChebConv, commuted:
//   Agg[row, f] = sum_{e: rows[e]=row} vals[e] * x_flat[512*cols[e] + f]   (f in [0,512))
//   out[row*1536 + j*192 + q] = sum_k Agg[row, j*64+k] * w[k*192+q] + bias[q&63]
// Gather runs on an fp16 copy of x (halves the L2-bandwidth wall); accumulation fp32.
#define N_VERTEX 2048
#define NNZ_MAX  98304
#define ROW_LEN  1536
#define KCOLS    192
#define NSUB     4
#define SUB_CAP  48
#define SLOTS    (NSUB * SUB_CAP)
#define TP       12            // transposed-Agg stride: 48B rows, 16B-aligned LDS.128
#define X_ELEMS  3145728

__device__ int    g_cnt[N_VERTEX * NSUB];
__device__ float2 g_edge[N_VERTEX * NSUB * SUB_CAP];   // (val, byte-offset bits)
__device__ __align__(16) __half g_xh[X_ELEMS];         // 6MB fp16 copy of x

typedef unsigned long long u64;
__device__ __forceinline__ u64 pk2(float a, float b) {
    u64 r; asm("mov.b64 %0, {%1, %2};" : "=l"(r) : "f"(a), "f"(b)); return r;
}
__device__ __forceinline__ u64 fma2(u64 a, u64 b, u64 c) {
    u64 d; asm("fma.rn.f32x2 %0, %1, %2, %3;" : "=l"(d) : "l"(a), "l"(b), "l"(c)); return d;
}
__device__ __forceinline__ u64 add2(u64 a, u64 b) {
    u64 d; asm("add.rn.f32x2 %0, %1, %2;" : "=l"(d) : "l"(a), "l"(b)); return d;
}

// x -> fp16, 8 elements per thread
__global__ void k_xhalf(const float* __restrict__ x) {
    int i = blockIdx.x * blockDim.x + threadIdx.x;
    if (i < X_ELEMS / 8) {
        float4 v0 = reinterpret_cast<const float4*>(x)[2 * i];
        float4 v1 = reinterpret_cast<const float4*>(x)[2 * i + 1];
        __half2 h0 = __floats2half2_rn(v0.x, v0.y);
        __half2 h1 = __floats2half2_rn(v0.z, v0.w);
        __half2 h2 = __floats2half2_rn(v1.x, v1.y);
        __half2 h3 = __floats2half2_rn(v1.z, v1.w);
        uint4 p;
        p.x = *reinterpret_cast<unsigned*>(&h0);
        p.y = *reinterpret_cast<unsigned*>(&h1);
        p.z = *reinterpret_cast<unsigned*>(&h2);
        p.w = *reinterpret_cast<unsigned*>(&h3);
        reinterpret_cast<uint4*>(g_xh)[i] = p;
    }
}

// Bucket scatter, 4-way split counters; stores BYTE offset into g_xh (col*512*2).
__global__ void k_scatter(const float* __restrict__ vals,
                          const int*   __restrict__ rows,
                          const int*   __restrict__ cols, int nnz) {
    int i = blockIdx.x * blockDim.x + threadIdx.x;
    if (i < nnz) {
        int r   = rows[i];
        int sub = i & (NSUB - 1);
        int p   = atomicAdd(&g_cnt[r * NSUB + sub], 1);
        if (p < SUB_CAP)
            g_edge[(r * NSUB + sub) * SUB_CAP + p] =
                make_float2(vals[i], __int_as_float(cols[i] * 1024));
    }
}

// Fused per-row kernel: fp16 gather-aggregate -> transposed smem -> f32x2 GEMM.
__global__ __launch_bounds__(256) void k_main(
    const float* __restrict__ w,
    const float* __restrict__ bias,
    float* __restrict__ out)
{
    __shared__ alignas(16) float sP[4][512];     // 4 gather partials (8KB)
    __shared__ alignas(16) float sT[64 * TP];    // transposed Agg: addr = TP*k + j
    __shared__ float2 sE[SLOTS];
    __shared__ int    sCnt[NSUB];

    const int row = blockIdx.x;
    const int tid = threadIdx.x;

    if (tid < NSUB) {
        int c = g_cnt[row * NSUB + tid];
        sCnt[tid] = (c > SUB_CAP) ? SUB_CAP : c;
        g_cnt[row * NSUB + tid] = 0;             // restore invariant for graph replay
    }
    __syncthreads();
    const int c0 = sCnt[0], c1 = sCnt[1], c2 = sCnt[2], c3 = sCnt[3];
    const int deg = c0 + c1 + c2 + c3;           // <= 192

    if (tid < deg) {
        int b, pos;
        if      (tid < c0)           { b = 0; pos = tid; }
        else if (tid < c0 + c1)      { b = 1; pos = tid - c0; }
        else if (tid < c0 + c1 + c2) { b = 2; pos = tid - c0 - c1; }
        else                         { b = 3; pos = tid - c0 - c1 - c2; }
        sE[tid] = g_edge[(row * NSUB + b) * SUB_CAP + pos];
    }
    __syncthreads();

    // ---- Phase 1: fp16 gather-aggregate; 64 lanes (8 halfs) x 4 edge-groups ----
    {
        const int lane = tid & 63;
        const int grp  = tid >> 6;
        float a0=0.f,a1=0.f,a2=0.f,a3=0.f,a4=0.f,a5=0.f,a6=0.f,a7=0.f;
        const char* xb = (const char*)g_xh + lane * 16;
        #pragma unroll 6
        for (int i = grp; i < deg; i += 4) {
            float2 ed = sE[i];                                    // LDS.64 broadcast
            uint4 d = *(const uint4*)(xb + __float_as_int(ed.y)); // LDG.128 (8 halfs)
            float v = ed.x;
            float2 f0 = __half22float2(*reinterpret_cast<__half2*>(&d.x));
            float2 f1 = __half22float2(*reinterpret_cast<__half2*>(&d.y));
            float2 f2 = __half22float2(*reinterpret_cast<__half2*>(&d.z));
            float2 f3 = __half22float2(*reinterpret_cast<__half2*>(&d.w));
            a0 = fmaf(v, f0.x, a0); a1 = fmaf(v, f0.y, a1);
            a2 = fmaf(v, f1.x, a2); a3 = fmaf(v, f1.y, a3);
            a4 = fmaf(v, f2.x, a4); a5 = fmaf(v, f2.y, a5);
            a6 = fmaf(v, f3.x, a6); a7 = fmaf(v, f3.y, a7);
        }
        float* sp = &sP[grp][8 * lane];
        *(float4*)(sp)     = make_float4(a0, a1, a2, a3);
        *(float4*)(sp + 4) = make_float4(a4, a5, a6, a7);
    }
    __syncthreads();

    // merge 4 partials + transpose into sT
    if (tid < 128) {
        const int f = 4 * tid;
        float4 p0 = *(const float4*)&sP[0][f];
        float4 p1 = *(const float4*)&sP[1][f];
        float4 p2 = *(const float4*)&sP[2][f];
        float4 p3 = *(const float4*)&sP[3][f];
        const int j  = f >> 6;
        const int k0 = f & 63;
        sT[TP * k0 + j]       = (p0.x + p1.x) + (p2.x + p3.x);
        sT[TP * (k0 + 1) + j] = (p0.y + p1.y) + (p2.y + p3.y);
        sT[TP * (k0 + 2) + j] = (p0.z + p1.z) + (p2.z + p3.z);
        sT[TP * (k0 + 3) + j] = (p0.w + p1.w) + (p2.w + p3.w);
    }
    __syncthreads();

    // ---- Phase 2: [8,64]@[64,192] + bias; j-paired f32x2 ----
    if (tid < KCOLS) {
        const int q = tid;
        u64 acc0 = 0ull, acc1 = 0ull, acc2 = 0ull, acc3 = 0ull;
        const float* wq = w + q;
        #pragma unroll 8
        for (int k = 0; k < 64; ++k) {
            float wv = __ldg(wq + k * KCOLS);                   // L1-resident, coalesced
            u64 wd = pk2(wv, wv);
            ulonglong2 b0 = *(const ulonglong2*)(sT + TP * k);      // (j0,j1),(j2,j3)
            ulonglong2 b1 = *(const ulonglong2*)(sT + TP * k + 4);  // (j4,j5),(j6,j7)
            acc0 = fma2(b0.x, wd, acc0);
            acc1 = fma2(b0.y, wd, acc1);
            acc2 = fma2(b1.x, wd, acc2);
            acc3 = fma2(b1.y, wd, acc3);
        }
        const float bv = __ldg(&bias[q & 63]);
        const u64 bd = pk2(bv, bv);
        acc0 = add2(acc0, bd); acc1 = add2(acc1, bd);
        acc2 = add2(acc2, bd); acc3 = add2(acc3, bd);
        float* op = out + (size_t)row * ROW_LEN + q;
        u64 accs[4] = {acc0, acc1, acc2, acc3};
        #pragma unroll
        for (int p = 0; p < 4; ++p) {
            float lo, hi;
            asm("mov.b64 {%0, %1}, %2;" : "=f"(lo), "=f"(hi) : "l"(accs[p]));
            op[(2 * p)     * KCOLS] = lo;
            op[(2 * p + 1) * KCOLS] = hi;
        }
    }
}

extern "C" void kernel_launch(void* const* d_in, const int* in_sizes, int n_in,
                              void* d_out, int out_size) {
    const float* x    = (const float*)d_in[0];
    const float* w    = (const float*)d_in[1];
    const float* bias = (const float*)d_in[2];
    const float* fv   = (const float*)d_in[3];
    const int*   fr   = (const int*)d_in[4];
    const int*   fc   = (const int*)d_in[5];
    int nnz = in_sizes[3];
    if (nnz > NNZ_MAX) nnz = NNZ_MAX;
    float* out = (float*)d_out;

    k_xhalf  <<<(X_ELEMS / 8 + 255) / 256, 256>>>(x);
    k_scatter<<<(nnz + 255) / 256, 256>>>(fv, fr, fc, nnz);
    k_main   <<<N_VERTEX, 256>>>(w, bias, out);
}

// round 8
// speedup vs baseline: 2.2484x; 1.0963x over previous
#include <cuda_runtime.h>
#include <cuda_fp16.h>
#include <cstdint>

// ChebConv, commuted:
//   Agg[row, f] = sum_{e: rows[e]=row} vals[e] * x_flat[512*cols[e] + f]   (f in [0,512))
//   out[row*1536 + j*192 + q] = sum_k Agg[row, j*64+k] * w[k*192+q] + bias[q&63]
// Gather runs on an fp16 copy of x; accumulation fp32.
#define N_VERTEX 2048
#define NNZ_MAX  98304
#define ROW_LEN  1536
#define KCOLS    192
#define NSUB     4
#define SUB_CAP  48
#define SLOTS    (NSUB * SUB_CAP)
#define TP       12            // transposed-Agg stride: 48B rows, 16B-aligned LDS.128
#define X_ELEMS  3145728
#define SCAT_BLK 384           // blocks 0..383 scatter; rest convert x

__device__ int    g_cnt[N_VERTEX * NSUB];
__device__ float2 g_edge[N_VERTEX * NSUB * SUB_CAP];   // (val, byte-offset bits)
__device__ __align__(16) __half g_xh[X_ELEMS];         // 6MB fp16 copy of x

typedef unsigned long long u64;
__device__ __forceinline__ u64 pk2(float a, float b) {
    u64 r; asm("mov.b64 %0, {%1, %2};" : "=l"(r) : "f"(a), "f"(b)); return r;
}
__device__ __forceinline__ u64 fma2(u64 a, u64 b, u64 c) {
    u64 d; asm("fma.rn.f32x2 %0, %1, %2, %3;" : "=l"(d) : "l"(a), "l"(b), "l"(c)); return d;
}
__device__ __forceinline__ u64 add2(u64 a, u64 b) {
    u64 d; asm("add.rn.f32x2 %0, %1, %2;" : "=l"(d) : "l"(a), "l"(b)); return d;
}
__device__ __forceinline__ uint4 ldg_nc_na(const void* p) {
    uint4 v;
    asm("ld.global.nc.L1::no_allocate.v4.u32 {%0,%1,%2,%3}, [%4];"
        : "=r"(v.x), "=r"(v.y), "=r"(v.z), "=r"(v.w) : "l"(p));
    return v;
}

// Fused prepass: blocks [0,SCAT_BLK) bucket-scatter edges; the rest convert x->fp16.
// The two halves touch disjoint data, so they overlap DRAM vs atomic latency.
__global__ void k_prep(const float* __restrict__ x,
                       const float* __restrict__ vals,
                       const int*   __restrict__ rows,
                       const int*   __restrict__ cols, int nnz) {
    if (blockIdx.x < SCAT_BLK) {
        int i = blockIdx.x * blockDim.x + threadIdx.x;
        if (i < nnz) {
            int r   = rows[i];
            int sub = i & (NSUB - 1);
            int p   = atomicAdd(&g_cnt[r * NSUB + sub], 1);
            if (p < SUB_CAP)
                g_edge[(r * NSUB + sub) * SUB_CAP + p] =
                    make_float2(vals[i], __int_as_float(cols[i] * 1024));
        }
    } else {
        int i = (blockIdx.x - SCAT_BLK) * blockDim.x + threadIdx.x;
        if (i < X_ELEMS / 8) {
            float4 v0 = reinterpret_cast<const float4*>(x)[2 * i];
            float4 v1 = reinterpret_cast<const float4*>(x)[2 * i + 1];
            __half2 h0 = __floats2half2_rn(v0.x, v0.y);
            __half2 h1 = __floats2half2_rn(v0.z, v0.w);
            __half2 h2 = __floats2half2_rn(v1.x, v1.y);
            __half2 h3 = __floats2half2_rn(v1.z, v1.w);
            uint4 p;
            p.x = *reinterpret_cast<unsigned*>(&h0);
            p.y = *reinterpret_cast<unsigned*>(&h1);
            p.z = *reinterpret_cast<unsigned*>(&h2);
            p.w = *reinterpret_cast<unsigned*>(&h3);
            reinterpret_cast<uint4*>(g_xh)[i] = p;
        }
    }
}

// Fused per-row kernel: fp16 gather-aggregate -> transposed smem -> f32x2 GEMM.
__global__ __launch_bounds__(256) void k_main(
    const float* __restrict__ w,
    const float* __restrict__ bias,
    float* __restrict__ out)
{
    __shared__ alignas(16) float sP[4][512];     // 4 gather partials (8KB)
    __shared__ alignas(16) float sT[64 * TP];    // transposed Agg: addr = TP*k + j
    __shared__ float2 sE[SLOTS];
    __shared__ int    sCnt[NSUB];

    const int row = blockIdx.x;
    const int tid = threadIdx.x;

    if (tid < NSUB) {
        int c = g_cnt[row * NSUB + tid];
        sCnt[tid] = (c > SUB_CAP) ? SUB_CAP : c;
        g_cnt[row * NSUB + tid] = 0;             // restore invariant for graph replay
    }
    __syncthreads();
    const int c0 = sCnt[0], c1 = sCnt[1], c2 = sCnt[2], c3 = sCnt[3];
    const int deg = c0 + c1 + c2 + c3;           // typically ~48, <= 192

    if (tid < deg) {
        int b, pos;
        if      (tid < c0)           { b = 0; pos = tid; }
        else if (tid < c0 + c1)      { b = 1; pos = tid - c0; }
        else if (tid < c0 + c1 + c2) { b = 2; pos = tid - c0 - c1; }
        else                         { b = 3; pos = tid - c0 - c1 - c2; }
        sE[tid] = g_edge[(row * NSUB + b) * SUB_CAP + pos];
    }
    __syncthreads();

    // ---- Phase 1: fp16 gather-aggregate; 64 lanes (8 halfs) x 4 edge-groups ----
    {
        const int lane = tid & 63;
        const int grp  = tid >> 6;
        float a0=0.f,a1=0.f,a2=0.f,a3=0.f,a4=0.f,a5=0.f,a6=0.f,a7=0.f;
        const char* xb = (const char*)g_xh + lane * 16;
        #pragma unroll 12
        for (int i = grp; i < deg; i += 4) {
            float2 ed = sE[i];                                    // LDS.64 broadcast
            uint4 d = ldg_nc_na(xb + __float_as_int(ed.y));       // LDG.128, L1 no-alloc
            float v = ed.x;
            float2 f0 = __half22float2(*reinterpret_cast<__half2*>(&d.x));
            float2 f1 = __half22float2(*reinterpret_cast<__half2*>(&d.y));
            float2 f2 = __half22float2(*reinterpret_cast<__half2*>(&d.z));
            float2 f3 = __half22float2(*reinterpret_cast<__half2*>(&d.w));
            a0 = fmaf(v, f0.x, a0); a1 = fmaf(v, f0.y, a1);
            a2 = fmaf(v, f1.x, a2); a3 = fmaf(v, f1.y, a3);
            a4 = fmaf(v, f2.x, a4); a5 = fmaf(v, f2.y, a5);
            a6 = fmaf(v, f3.x, a6); a7 = fmaf(v, f3.y, a7);
        }
        float* sp = &sP[grp][8 * lane];
        *(float4*)(sp)     = make_float4(a0, a1, a2, a3);
        *(float4*)(sp + 4) = make_float4(a4, a5, a6, a7);
    }
    __syncthreads();

    // merge 4 partials + transpose into sT
    if (tid < 128) {
        const int f = 4 * tid;
        float4 p0 = *(const float4*)&sP[0][f];
        float4 p1 = *(const float4*)&sP[1][f];
        float4 p2 = *(const float4*)&sP[2][f];
        float4 p3 = *(const float4*)&sP[3][f];
        const int j  = f >> 6;
        const int k0 = f & 63;
        sT[TP * k0 + j]       = (p0.x + p1.x) + (p2.x + p3.x);
        sT[TP * (k0 + 1) + j] = (p0.y + p1.y) + (p2.y + p3.y);
        sT[TP * (k0 + 2) + j] = (p0.z + p1.z) + (p2.z + p3.z);
        sT[TP * (k0 + 3) + j] = (p0.w + p1.w) + (p2.w + p3.w);
    }
    __syncthreads();

    // ---- Phase 2: [8,64]@[64,192] + bias; j-paired f32x2 ----
    if (tid < KCOLS) {
        const int q = tid;
        u64 acc0 = 0ull, acc1 = 0ull, acc2 = 0ull, acc3 = 0ull;
        const float* wq = w + q;
        #pragma unroll 8
        for (int k = 0; k < 64; ++k) {
            float wv = __ldg(wq + k * KCOLS);                   // L1-resident, coalesced
            u64 wd = pk2(wv, wv);
            ulonglong2 b0 = *(const ulonglong2*)(sT + TP * k);      // (j0,j1),(j2,j3)
            ulonglong2 b1 = *(const ulonglong2*)(sT + TP * k + 4);  // (j4,j5),(j6,j7)
            acc0 = fma2(b0.x, wd, acc0);
            acc1 = fma2(b0.y, wd, acc1);
            acc2 = fma2(b1.x, wd, acc2);
            acc3 = fma2(b1.y, wd, acc3);
        }
        const float bv = __ldg(&bias[q & 63]);
        const u64 bd = pk2(bv, bv);
        acc0 = add2(acc0, bd); acc1 = add2(acc1, bd);
        acc2 = add2(acc2, bd); acc3 = add2(acc3, bd);
        float* op = out + (size_t)row * ROW_LEN + q;
        u64 accs[4] = {acc0, acc1, acc2, acc3};
        #pragma unroll
        for (int p = 0; p < 4; ++p) {
            float lo, hi;
            asm("mov.b64 {%0, %1}, %2;" : "=f"(lo), "=f"(hi) : "l"(accs[p]));
            op[(2 * p)     * KCOLS] = lo;
            op[(2 * p + 1) * KCOLS] = hi;
        }
    }
}

extern "C" void kernel_launch(void* const* d_in, const int* in_sizes, int n_in,
                              void* d_out, int out_size) {
    const float* x    = (const float*)d_in[0];
    const float* w    = (const float*)d_in[1];
    const float* bias = (const float*)d_in[2];
    const float* fv   = (const float*)d_in[3];
    const int*   fr   = (const int*)d_in[4];
    const int*   fc   = (const int*)d_in[5];
    int nnz = in_sizes[3];
    if (nnz > NNZ_MAX) nnz = NNZ_MAX;
    float* out = (float*)d_out;

    const int conv_blocks = (X_ELEMS / 8 + 255) / 256;   // 1536
    k_prep<<<SCAT_BLK + conv_blocks, 256>>>(x, fv, fr, fc, nnz);
    k_main<<<N_VERTEX, 256>>>(w, bias, out);
}